// round 8
// baseline (speedup 1.0000x reference)
#include <cuda_runtime.h>
#include <cuda_bf16.h>

// FieldAwareFM: out[b] = sum over 780 field pairs (a<b) of
//   dot(x[b, a, b-1, :], x[b, b, a, :]),  x = input reshaped (bs, 40, 39, 16).
//
// R8 = R7 (persistent double-buffered TMA pipeline) +
//  * grid = 128 so 2048/128 = 16 rows/SM EXACTLY (R7's 152-SM grid had a
//    13-vs-14 ragged tail, ~4%),
//  * deep L2 prefetch: cp.async.bulk.prefetch.L2.global for row k+4 issued at
//    the top of row k's compute (~2 row-periods ahead) keeps the DRAM queue
//    continuously deep; the later TMA smem-fills become L2 hits,
//  * refill TMA for row k+2 issued right after the last sbuf read (before
//    the reduction), not after it.

#define NUM_FIELDS 40
#define COLS 39
#define EMB 16
#define ROW_FLOATS (NUM_FIELDS * COLS * EMB)      // 24960
#define ROW_F4 (ROW_FLOATS / 4)                   // 6240
#define ROW_BYTES (ROW_F4 * 16)                   // 99840
#define NPAIRS 780
#define WORK (NPAIRS * 4)                         // 3120 float4-pair items
#define THREADS 512
#define COMP_ITERS (WORK / THREADS)               // 6
#define COMP_REM (WORK - COMP_ITERS * THREADS)    // 48
#define GRID 128
#define PREF_AHEAD 4

extern __shared__ __align__(128) float4 sbuf[];   // 2 * ROW_F4 float4

__device__ __forceinline__ void tma_issue_row(unsigned mbar_addr,
                                              float4* sdst,
                                              const float4* gsrc)
{
    unsigned d = (unsigned)__cvta_generic_to_shared(sdst);
    asm volatile("mbarrier.arrive.expect_tx.shared.b64 _, [%0], %1;"
                 :: "r"(mbar_addr), "r"(ROW_BYTES) : "memory");
    asm volatile(
        "cp.async.bulk.shared::cta.global.mbarrier::complete_tx::bytes"
        " [%0], [%1], %2, [%3];"
        :: "r"(d), "l"(gsrc), "r"(ROW_BYTES), "r"(mbar_addr) : "memory");
}

__device__ __forceinline__ void l2_prefetch_row(const float4* gsrc)
{
    asm volatile("cp.async.bulk.prefetch.L2.global [%0], %1;"
                 :: "l"(gsrc), "r"(ROW_BYTES) : "memory");
}

__device__ __forceinline__ void mbar_wait(unsigned mbar_addr, unsigned parity)
{
    unsigned done;
    asm volatile(
        "{\n\t.reg .pred p;\n\t"
        "mbarrier.try_wait.parity.acquire.cta.shared::cta.b64 p, [%1], %2;\n\t"
        "selp.b32 %0, 1, 0, p;\n\t}"
        : "=r"(done) : "r"(mbar_addr), "r"(parity) : "memory");
    if (!done) {
        asm volatile(
            "{\n\t.reg .pred P1;\n\t"
            "W_%=:\n\t"
            "mbarrier.try_wait.parity.acquire.cta.shared::cta.b64 P1, [%0], %1, 0x989680;\n\t"
            "@P1 bra.uni D_%=;\n\t"
            "bra.uni W_%=;\n\t"
            "D_%=:\n\t}"
            :: "r"(mbar_addr), "r"(parity) : "memory");
    }
}

__global__ __launch_bounds__(THREADS, 1)
void ffm_persistent_kernel(const float* __restrict__ in,
                           float* __restrict__ out, int nrows)
{
    __shared__ unsigned int pair_tab[NPAIRS];     // (fA*4) | (fB*4 << 16)
    __shared__ float warp_sums[THREADS / 32];
    __shared__ __align__(8) unsigned long long mbar[2];

    const int tid  = threadIdx.x;
    const int nblk = gridDim.x;
    const int myrows = (nrows - blockIdx.x + nblk - 1) / nblk;   // 16 for all
    const float4* __restrict__ gin = reinterpret_cast<const float4*>(in);

    if (tid == 0) {
        #pragma unroll
        for (int c = 0; c < 2; ++c) {
            unsigned m = (unsigned)__cvta_generic_to_shared(&mbar[c]);
            asm volatile("mbarrier.init.shared.b64 [%0], %1;"
                         :: "r"(m), "r"(1) : "memory");
        }
    }

    // ---- pair table, built once per block ----
    for (int s = tid; s < NPAIRS; s += THREADS) {
        int b = (int)((1.0f + sqrtf((float)(8 * s + 1))) * 0.5f);
        if (b * (b - 1) / 2 > s)       --b;
        else if ((b + 1) * b / 2 <= s) ++b;
        const int a  = s - b * (b - 1) / 2;           // a < b
        const int fA = a * COLS + (b - 1);            // x[a][b-1]
        const int fB = b * COLS + a;                  // x[b][a]
        pair_tab[s] = (unsigned int)(fA * 4) | ((unsigned int)(fB * 4) << 16);
    }
    __syncthreads();

    const unsigned m0 = (unsigned)__cvta_generic_to_shared(&mbar[0]);
    const unsigned m1 = (unsigned)__cvta_generic_to_shared(&mbar[1]);

    // ---- prologue: TMA rows 0,1; L2-prefetch rows 2..PREF_AHEAD-1 ----
    if (tid == 0) {
        if (myrows > 0)
            tma_issue_row(m0, sbuf, gin + (size_t)blockIdx.x * ROW_F4);
        if (myrows > 1)
            tma_issue_row(m1, sbuf + ROW_F4,
                          gin + (size_t)(blockIdx.x + nblk) * ROW_F4);
        for (int r = 2; r < PREF_AHEAD && r < myrows; ++r)
            l2_prefetch_row(gin + (size_t)(blockIdx.x + (size_t)r * nblk) * ROW_F4);
    }

    for (int k = 0; k < myrows; ++k) {
        const int cur = k & 1;
        const unsigned parity = (unsigned)((k >> 1) & 1);
        mbar_wait(cur ? m1 : m0, parity);

        // keep the DRAM->L2 stream deep: prefetch row k+PREF_AHEAD now
        if (tid == 0 && k + PREF_AHEAD < myrows)
            l2_prefetch_row(gin + (size_t)(blockIdx.x +
                            (size_t)(k + PREF_AHEAD) * nblk) * ROW_F4);

        const float4* __restrict__ srow = sbuf + cur * ROW_F4;
        float acc = 0.0f;
        int w = tid;
        #pragma unroll
        for (int it = 0; it < COMP_ITERS; ++it, w += THREADS) {
            const int s  = w >> 2;
            const int d4 = w & 3;
            const unsigned int pk = pair_tab[s];
            const float4 a = srow[(int)(pk & 0xffffu) + d4];
            const float4 p = srow[(int)(pk >> 16) + d4];
            acc = fmaf(a.x, p.x, acc);
            acc = fmaf(a.y, p.y, acc);
            acc = fmaf(a.z, p.z, acc);
            acc = fmaf(a.w, p.w, acc);
        }
        if (tid < COMP_REM) {
            const int s  = w >> 2;
            const int d4 = w & 3;
            const unsigned int pk = pair_tab[s];
            const float4 a = srow[(int)(pk & 0xffffu) + d4];
            const float4 p = srow[(int)(pk >> 16) + d4];
            acc = fmaf(a.x, p.x, acc);
            acc = fmaf(a.y, p.y, acc);
            acc = fmaf(a.z, p.z, acc);
            acc = fmaf(a.w, p.w, acc);
        }

        __syncthreads();   // all sbuf[cur] reads complete

        // ---- refill freed buffer with row k+2 IMMEDIATELY ----
        if (tid == 0 && k + 2 < myrows)
            tma_issue_row(cur ? m1 : m0, sbuf + cur * ROW_F4,
                          gin + (size_t)(blockIdx.x + (size_t)(k + 2) * nblk) * ROW_F4);

        // ---- block reduction for this row (registers + warp_sums only) ----
        #pragma unroll
        for (int o = 16; o > 0; o >>= 1)
            acc += __shfl_down_sync(0xffffffffu, acc, o);
        if ((tid & 31) == 0)
            warp_sums[tid >> 5] = acc;
        __syncthreads();
        if (tid < (THREADS / 32)) {
            acc = warp_sums[tid];
            #pragma unroll
            for (int o = (THREADS / 64); o > 0; o >>= 1)
                acc += __shfl_down_sync(0x0000ffffu, acc, o);
            if (tid == 0)
                out[blockIdx.x + (size_t)k * nblk] = acc;
        }
        // no extra sync needed: next iteration's mbar_wait orders the next
        // sbuf reads, and warp_sums is re-written only after the next
        // __syncthreads in that iteration.
        __syncthreads();
    }
}

extern "C" void kernel_launch(void* const* d_in, const int* in_sizes, int n_in,
                              void* d_out, int out_size)
{
    const float* in = (const float*)d_in[0];
    float* out = (float*)d_out;
    const int bs = in_sizes[0] / ROW_FLOATS;   // 2048

    cudaFuncSetAttribute(ffm_persistent_kernel,
                         cudaFuncAttributeMaxDynamicSharedMemorySize,
                         2 * ROW_BYTES);
    ffm_persistent_kernel<<<GRID, THREADS, 2 * ROW_BYTES>>>(in, out, bs);
}

// round 9
// speedup vs baseline: 1.0481x; 1.0481x over previous
#include <cuda_runtime.h>
#include <cuda_bf16.h>

// FieldAwareFM: out[b] = sum over 780 field pairs (a<b) of
//   dot(x[b, a, b-1, :], x[b, b, a, :]),  x = input reshaped (bs, 40, 39, 16).
//
// R9 = R7 (persistent double-buffered TMA pipeline, grid=152) with a deeper
// per-SM copy queue:
//  * each row is fetched as FOUR 24960-B bulk copies completing on one
//    mbarrier (expect_tx = full row) -> 4-8 TMA ops in flight per SM instead
//    of 1-2 (R8 proved per-SM streams weren't at their ceiling; aggregate
//    depth was the limit),
//  * refill for row k+2 issued immediately after the sbuf-read sync, before
//    the reduction,
//  * no L2 prefetch (measured no-op in R8), grid back to 152 (128 idled
//    engines and regressed).

#define NUM_FIELDS 40
#define COLS 39
#define EMB 16
#define ROW_FLOATS (NUM_FIELDS * COLS * EMB)      // 24960
#define ROW_F4 (ROW_FLOATS / 4)                   // 6240
#define ROW_BYTES (ROW_F4 * 16)                   // 99840
#define QCOPIES 4
#define QBYTES (ROW_BYTES / QCOPIES)              // 24960
#define QF4 (ROW_F4 / QCOPIES)                    // 1560
#define NPAIRS 780
#define WORK (NPAIRS * 4)                         // 3120 float4-pair items
#define THREADS 512
#define COMP_ITERS (WORK / THREADS)               // 6
#define COMP_REM (WORK - COMP_ITERS * THREADS)    // 48

extern __shared__ __align__(128) float4 sbuf[];   // 2 * ROW_F4 float4

__device__ __forceinline__ void tma_issue_row(unsigned mbar_addr,
                                              float4* sdst,
                                              const float4* gsrc)
{
    asm volatile("mbarrier.arrive.expect_tx.shared.b64 _, [%0], %1;"
                 :: "r"(mbar_addr), "r"(ROW_BYTES) : "memory");
    #pragma unroll
    for (int q = 0; q < QCOPIES; ++q) {
        unsigned d = (unsigned)__cvta_generic_to_shared(sdst + q * QF4);
        asm volatile(
            "cp.async.bulk.shared::cta.global.mbarrier::complete_tx::bytes"
            " [%0], [%1], %2, [%3];"
            :: "r"(d), "l"(gsrc + q * QF4), "r"(QBYTES), "r"(mbar_addr)
            : "memory");
    }
}

__device__ __forceinline__ void mbar_wait(unsigned mbar_addr, unsigned parity)
{
    unsigned done;
    asm volatile(
        "{\n\t.reg .pred p;\n\t"
        "mbarrier.try_wait.parity.acquire.cta.shared::cta.b64 p, [%1], %2;\n\t"
        "selp.b32 %0, 1, 0, p;\n\t}"
        : "=r"(done) : "r"(mbar_addr), "r"(parity) : "memory");
    if (!done) {
        asm volatile(
            "{\n\t.reg .pred P1;\n\t"
            "W_%=:\n\t"
            "mbarrier.try_wait.parity.acquire.cta.shared::cta.b64 P1, [%0], %1, 0x989680;\n\t"
            "@P1 bra.uni D_%=;\n\t"
            "bra.uni W_%=;\n\t"
            "D_%=:\n\t}"
            :: "r"(mbar_addr), "r"(parity) : "memory");
    }
}

__global__ __launch_bounds__(THREADS, 1)
void ffm_persistent_kernel(const float* __restrict__ in,
                           float* __restrict__ out, int nrows)
{
    __shared__ unsigned int pair_tab[NPAIRS];     // (fA*4) | (fB*4 << 16)
    __shared__ float warp_sums[THREADS / 32];
    __shared__ __align__(8) unsigned long long mbar[2];

    const int tid  = threadIdx.x;
    const int nblk = gridDim.x;
    const int myrows = (nrows - blockIdx.x + nblk - 1) / nblk;
    const float4* __restrict__ gin = reinterpret_cast<const float4*>(in);

    if (tid == 0) {
        #pragma unroll
        for (int c = 0; c < 2; ++c) {
            unsigned m = (unsigned)__cvta_generic_to_shared(&mbar[c]);
            asm volatile("mbarrier.init.shared.b64 [%0], %1;"
                         :: "r"(m), "r"(1) : "memory");
        }
    }

    // ---- pair table, built once per block ----
    for (int s = tid; s < NPAIRS; s += THREADS) {
        int b = (int)((1.0f + sqrtf((float)(8 * s + 1))) * 0.5f);
        if (b * (b - 1) / 2 > s)       --b;
        else if ((b + 1) * b / 2 <= s) ++b;
        const int a  = s - b * (b - 1) / 2;           // a < b
        const int fA = a * COLS + (b - 1);            // x[a][b-1]
        const int fB = b * COLS + a;                  // x[b][a]
        pair_tab[s] = (unsigned int)(fA * 4) | ((unsigned int)(fB * 4) << 16);
    }
    __syncthreads();

    const unsigned m0 = (unsigned)__cvta_generic_to_shared(&mbar[0]);
    const unsigned m1 = (unsigned)__cvta_generic_to_shared(&mbar[1]);

    // ---- prologue: enqueue rows 0 and 1 ----
    if (tid == 0) {
        if (myrows > 0)
            tma_issue_row(m0, sbuf, gin + (size_t)blockIdx.x * ROW_F4);
        if (myrows > 1)
            tma_issue_row(m1, sbuf + ROW_F4,
                          gin + (size_t)(blockIdx.x + nblk) * ROW_F4);
    }

    for (int k = 0; k < myrows; ++k) {
        const int cur = k & 1;
        const unsigned parity = (unsigned)((k >> 1) & 1);
        mbar_wait(cur ? m1 : m0, parity);

        const float4* __restrict__ srow = sbuf + cur * ROW_F4;
        float acc = 0.0f;
        int w = tid;
        #pragma unroll
        for (int it = 0; it < COMP_ITERS; ++it, w += THREADS) {
            const int s  = w >> 2;
            const int d4 = w & 3;
            const unsigned int pk = pair_tab[s];
            const float4 a = srow[(int)(pk & 0xffffu) + d4];
            const float4 p = srow[(int)(pk >> 16) + d4];
            acc = fmaf(a.x, p.x, acc);
            acc = fmaf(a.y, p.y, acc);
            acc = fmaf(a.z, p.z, acc);
            acc = fmaf(a.w, p.w, acc);
        }
        if (tid < COMP_REM) {
            const int s  = w >> 2;
            const int d4 = w & 3;
            const unsigned int pk = pair_tab[s];
            const float4 a = srow[(int)(pk & 0xffffu) + d4];
            const float4 p = srow[(int)(pk >> 16) + d4];
            acc = fmaf(a.x, p.x, acc);
            acc = fmaf(a.y, p.y, acc);
            acc = fmaf(a.z, p.z, acc);
            acc = fmaf(a.w, p.w, acc);
        }

        __syncthreads();   // all sbuf[cur] reads complete

        // ---- refill freed buffer with row k+2 IMMEDIATELY ----
        if (tid == 0 && k + 2 < myrows)
            tma_issue_row(cur ? m1 : m0, sbuf + cur * ROW_F4,
                          gin + (size_t)(blockIdx.x + (size_t)(k + 2) * nblk) * ROW_F4);

        // ---- block reduction for this row ----
        #pragma unroll
        for (int o = 16; o > 0; o >>= 1)
            acc += __shfl_down_sync(0xffffffffu, acc, o);
        if ((tid & 31) == 0)
            warp_sums[tid >> 5] = acc;
        __syncthreads();
        if (tid < (THREADS / 32)) {
            acc = warp_sums[tid];
            #pragma unroll
            for (int o = (THREADS / 64); o > 0; o >>= 1)
                acc += __shfl_down_sync(0x0000ffffu, acc, o);
            if (tid == 0)
                out[blockIdx.x + (size_t)k * nblk] = acc;
        }
        __syncthreads();   // protect warp_sums for the next iteration
    }
}

extern "C" void kernel_launch(void* const* d_in, const int* in_sizes, int n_in,
                              void* d_out, int out_size)
{
    const float* in = (const float*)d_in[0];
    float* out = (float*)d_out;
    const int bs = in_sizes[0] / ROW_FLOATS;   // 2048

    int sms = 148;
    cudaDeviceGetAttribute(&sms, cudaDevAttrMultiProcessorCount, 0);

    cudaFuncSetAttribute(ffm_persistent_kernel,
                         cudaFuncAttributeMaxDynamicSharedMemorySize,
                         2 * ROW_BYTES);
    ffm_persistent_kernel<<<sms, THREADS, 2 * ROW_BYTES>>>(in, out, bs);
}